// round 6
// baseline (speedup 1.0000x reference)
#include <cuda_runtime.h>

// DeepPoly ReLU relaxation, elementwise over N=16,777,216 floats.
// inputs: lb, ub, alpha (fp32, N each). output: [out_lb (N) | out_ub (N)] fp32.
//
// HBM-roofline-saturated: 20 B/elem mandatory traffic (3 reads + 2 writes,
// no reuse) = 336 MB @ ~6.4-6.5 TB/s achieved (~81% of 8 TB/s spec).
// Measured across R1-R4: cache hints, per-thread batching, and bounds-check
// elision are all neutral; 2x batching regresses (occ 80%->60%). The LTS
// throughput cap is path-independent (B300 microarch), so smem/TMA staging
// cannot beat plain LDG.128/STG.128 here.
//
// Final shape: 1 float4/thread, 29 regs, 512-thread blocks (8192 blocks,
// same 2048 thr/SM occupancy, half the CTA-scheduling granularity), exact
// grid, plain loads/stores (empirical best, R1).

__global__ __launch_bounds__(512) void verify_relu_kernel(
    const float4* __restrict__ lb4,
    const float4* __restrict__ ub4,
    const float4* __restrict__ al4,
    float4* __restrict__ olb4,
    float4* __restrict__ oub4)
{
    int i = blockIdx.x * 512 + threadIdx.x;   // grid is exact: no bounds check

    float4 lb = lb4[i];
    float4 ub = ub4[i];
    float4 al = al4[i];

    float4 olb, oub;

    #pragma unroll
    for (int k = 0; k < 4; k++) {
        float l = (&lb.x)[k];
        float u = (&ub.x)[k];
        float a = (&al.x)[k];

        float ca    = fminf(fmaxf(a, 0.0f), 1.0f);
        float slope = fmaxf(u / (u - l), 0.0f);

        float uc_diag = (l > 0.0f) ? 1.0f : slope;
        float uc_bias = (l > 0.0f) ? 0.0f : (-(slope * l));
        float lc_diag = (u < 0.0f) ? 0.0f : ca;

        (&olb.x)[k] = l * lc_diag;
        (&oub.x)[k] = fmaf(u, uc_diag, uc_bias);
    }

    olb4[i] = olb;
    oub4[i] = oub;
}

extern "C" void kernel_launch(void* const* d_in, const int* in_sizes, int n_in,
                              void* d_out, int out_size) {
    const float* lb    = (const float*)d_in[0];
    const float* ub    = (const float*)d_in[1];
    const float* alpha = (const float*)d_in[2];
    float* out = (float*)d_out;

    int n  = in_sizes[0];        // 16777216
    int n4 = n / 4;              // 4194304

    float* out_lb = out;
    float* out_ub = out + n;

    int threads = 512;
    int blocks  = n4 / threads;  // 8192, exact (n4 % 512 == 0)

    verify_relu_kernel<<<blocks, threads>>>(
        (const float4*)lb, (const float4*)ub, (const float4*)alpha,
        (float4*)out_lb, (float4*)out_ub);
}

// round 8
// speedup vs baseline: 1.0053x; 1.0053x over previous
#include <cuda_runtime.h>

// DeepPoly ReLU relaxation, elementwise over N=16,777,216 floats.
// inputs: lb, ub, alpha (fp32, N each). output: [out_lb (N) | out_ub (N)] fp32.
//
// HBM-roofline-saturated. 20 B/elem mandatory traffic (3 reads + 2 writes,
// no reuse) = 336 MB @ ~6.5 TB/s achieved (~82% of 8 TB/s spec).
//
// Config sweep ledger (R1-R5): cache hints neutral; 2x/thread batching
// regresses (regs 29->40, occ 80->60%); 512-thr blocks regress (occ 75.8%);
// exact-grid elision neutral. The LTS cap is path-independent (B300
// microarch), so smem/TMA staging cannot beat plain LDG.128/STG.128.
// This is the measured-optimal R1 configuration: 256 thr/block, 16384
// blocks, 1 float4/thread, 29 regs, occ ~80%, DRAM ~82%.
// (R6 bench was an infra failure — container, not kernel; resubmitting.)

__global__ __launch_bounds__(256) void verify_relu_kernel(
    const float4* __restrict__ lb4,
    const float4* __restrict__ ub4,
    const float4* __restrict__ al4,
    float4* __restrict__ olb4,
    float4* __restrict__ oub4,
    int n4)
{
    int i = blockIdx.x * blockDim.x + threadIdx.x;
    if (i >= n4) return;

    float4 lb = lb4[i];
    float4 ub = ub4[i];
    float4 al = al4[i];

    float4 olb, oub;

    #pragma unroll
    for (int k = 0; k < 4; k++) {
        float l = (&lb.x)[k];
        float u = (&ub.x)[k];
        float a = (&al.x)[k];

        float ca    = fminf(fmaxf(a, 0.0f), 1.0f);
        float slope = fmaxf(u / (u - l), 0.0f);

        float uc_diag = (l > 0.0f) ? 1.0f : slope;
        float uc_bias = (l > 0.0f) ? 0.0f : (-(slope * l));
        float lc_diag = (u < 0.0f) ? 0.0f : ca;

        (&olb.x)[k] = l * lc_diag;
        (&oub.x)[k] = fmaf(u, uc_diag, uc_bias);
    }

    olb4[i] = olb;
    oub4[i] = oub;
}

extern "C" void kernel_launch(void* const* d_in, const int* in_sizes, int n_in,
                              void* d_out, int out_size) {
    const float* lb    = (const float*)d_in[0];
    const float* ub    = (const float*)d_in[1];
    const float* alpha = (const float*)d_in[2];
    float* out = (float*)d_out;

    int n  = in_sizes[0];        // 16777216
    int n4 = n / 4;              // 4194304

    float* out_lb = out;
    float* out_ub = out + n;

    int threads = 256;
    int blocks  = (n4 + threads - 1) / threads;   // 16384

    verify_relu_kernel<<<blocks, threads>>>(
        (const float4*)lb, (const float4*)ub, (const float4*)alpha,
        (float4*)out_lb, (float4*)out_ub, n4);
}

// round 9
// speedup vs baseline: 1.0174x; 1.0120x over previous
#include <cuda_runtime.h>

// DeepPoly ReLU relaxation, elementwise over N=16,777,216 floats.
// inputs: lb, ub, alpha (fp32, N each). output: [out_lb (N) | out_ub (N)] fp32.
//
// HBM-roofline-saturated — TERMINAL KERNEL.
// 20 B/elem mandatory traffic (3 reads + 2 writes, no reuse) = 336 MB
// @ 6.3-6.5 TB/s achieved (~80-82% of 8 TB/s spec). Residual gap is DRAM
// read/write turnaround on a 3:2 mix; per B300 microarch the LTS cap is
// path-independent (LDG.cv == TMA) and HBM striding is not a lever, so no
// software path exceeds plain LDG.128/STG.128 here.
//
// Config ledger (R1-R8):
//   R1/R8 (this config, benched twice): 53.31 / 53.98 us  -> ±0.7us noise
//   R3 (+ldcs/stcs):            53.34  neutral
//   R4 (exact grid, stcs):      53.54  neutral
//   R2 (2 quads/thread):        53.63  regress (regs 40, occ 60%)
//   R5 (512-thr blocks):        54.27  regress (occ 75.8%)
// Shape: 256 thr/block, 16384 blocks, 1 float4/thread, 29 regs, occ ~80%.

__global__ __launch_bounds__(256) void verify_relu_kernel(
    const float4* __restrict__ lb4,
    const float4* __restrict__ ub4,
    const float4* __restrict__ al4,
    float4* __restrict__ olb4,
    float4* __restrict__ oub4,
    int n4)
{
    int i = blockIdx.x * blockDim.x + threadIdx.x;
    if (i >= n4) return;

    float4 lb = lb4[i];
    float4 ub = ub4[i];
    float4 al = al4[i];

    float4 olb, oub;

    #pragma unroll
    for (int k = 0; k < 4; k++) {
        float l = (&lb.x)[k];
        float u = (&ub.x)[k];
        float a = (&al.x)[k];

        float ca    = fminf(fmaxf(a, 0.0f), 1.0f);
        float slope = fmaxf(u / (u - l), 0.0f);

        float uc_diag = (l > 0.0f) ? 1.0f : slope;
        float uc_bias = (l > 0.0f) ? 0.0f : (-(slope * l));
        float lc_diag = (u < 0.0f) ? 0.0f : ca;

        (&olb.x)[k] = l * lc_diag;
        (&oub.x)[k] = fmaf(u, uc_diag, uc_bias);
    }

    olb4[i] = olb;
    oub4[i] = oub;
}

extern "C" void kernel_launch(void* const* d_in, const int* in_sizes, int n_in,
                              void* d_out, int out_size) {
    const float* lb    = (const float*)d_in[0];
    const float* ub    = (const float*)d_in[1];
    const float* alpha = (const float*)d_in[2];
    float* out = (float*)d_out;

    int n  = in_sizes[0];        // 16777216
    int n4 = n / 4;              // 4194304

    float* out_lb = out;
    float* out_ub = out + n;

    int threads = 256;
    int blocks  = (n4 + threads - 1) / threads;   // 16384

    verify_relu_kernel<<<blocks, threads>>>(
        (const float4*)lb, (const float4*)ub, (const float4*)alpha,
        (float4*)out_lb, (float4*)out_ub, n4);
}